// round 15
// baseline (speedup 1.0000x reference)
#include <cuda_runtime.h>

// MultiStageFIRFilter: y = x + sum_{a=1..20} xa_a,
//   xa_a[b,t] = (1/a) * sum_{k=0..24} mc[b,t,k] * xa_{a-1}[b,t-k]  (xa_0 = x, causal)
//
// Fused halo-recompute kernel, R=1, 1024 threads (32 warps/SM — RF-feasible
// because R=1 needs only 25 coeff regs). Window read as 13 uniform LDS.64
// from the even-aligned base e = tid & ~1 (adjacent threads broadcast-share
// words -> 1 wavefront per LDS.64). Thread parity is folded into a pre-shifted
// reversed coefficient array cc[26] built once in the prologue:
//   out(p) = sum_m cc[m] * w26[m],  w26[m] = val(e - 24 + m),
//   cc[m] = c[pi + 24 - m] (pi = tid & 1), out-of-range -> 0.

#define NB      4
#define NT      16384
#define M       25
#define STAGES  20
#define HALO    480       // STAGES * 24
#define THREADS 1024
#define EXT     1024      // 1 position per thread
#define TILE    544       // EXT - HALO
#define PAD     24
#define NTILES  31        // ceil(16384 / 544)

__global__ __launch_bounds__(THREADS, 1)
void fir_kernel(const float* __restrict__ x, const float* __restrict__ mc,
                float* __restrict__ out)
{
    __shared__ __align__(16) float s0[PAD + EXT];   // 1048 floats, idx 0..1047
    __shared__ __align__(16) float s1[PAD + EXT];

    const int tile = blockIdx.x % NTILES;
    const int b    = blockIdx.x / NTILES;
    const int t0   = tile * TILE;
    const int tid  = threadIdx.x;
    const int e    = tid & ~1;             // even-aligned window base
    const int p    = t0 - HALO + tid;      // this thread's global position
    const size_t rowbase = (size_t)b * NT;
    const bool valid = (p >= 0 && p < NT);

    if (tid < PAD) { s0[tid] = 0.0f; s1[tid] = 0.0f; }   // ghost zeros

    // ---- coefficients c[k] = mc[p][k]; invalid row -> 0 (ghost/overhang) ----
    float c[25];
    if (valid) {
        const float* g = mc + (rowbase + (size_t)p) * M;
        #pragma unroll
        for (int k = 0; k < 25; k++) c[k] = g[k];
    } else {
        #pragma unroll
        for (int k = 0; k < 25; k++) c[k] = 0.0f;
    }
    // ---- parity-shifted reversed coefficients: cc[m] = c[(tid&1) + 24 - m] ----
    float cc[26];
    if (tid & 1) {
        cc[0] = 0.0f;                       // would be c[25]
        #pragma unroll
        for (int m = 1; m < 26; m++) cc[m] = c[25 - m];
    } else {
        cc[25] = 0.0f;                      // would be c[-1]
        #pragma unroll
        for (int m = 0; m < 25; m++) cc[m] = c[24 - m];
    }

    // ---- stage 0: xa = x ----
    float v = valid ? x[rowbase + p] : 0.0f;
    float y = v;
    s0[PAD + tid] = v;
    __syncthreads();

    float* cur = s0;
    float* nxt = s1;

    #pragma unroll
    for (int a = 1; a <= STAGES; a++) {
        const float inv = 1.0f / (float)a;            // compile-time constant
        // w26[m] = val(e - 24 + m) = cur[e + m], m = 0..25 (13 LDS.64, broadcast-
        // shared between the even/odd thread pair -> ~1 wavefront each).
        float2 W[13];
        const float2* wp = (const float2*)(cur + e);  // 8B-aligned (e even)
        #pragma unroll
        for (int m = 0; m < 13; m++) W[m] = wp[m];

        // out = sum_m cc[m] * w26[m]; two independent 13-FMA chains
        float pA = 0.0f, pB = 0.0f;
        #pragma unroll
        for (int m = 0; m < 13; m += 2) {             // even pair index -> chain A
            pA = fmaf(cc[2*m],     W[m].x, pA);
            pA = fmaf(cc[2*m + 1], W[m].y, pA);
        }
        #pragma unroll
        for (int m = 1; m < 13; m += 2) {             // odd pair index -> chain B
            pB = fmaf(cc[2*m],     W[m].x, pB);
            pB = fmaf(cc[2*m + 1], W[m].y, pB);
        }
        const float acc = (pA + pB) * inv;

        y += acc;
        v = acc;
        nxt[PAD + tid] = v;
        __syncthreads();
        float* tmp = cur; cur = nxt; nxt = tmp;
    }

    // ---- write owned (non-halo) output ----
    if (tid >= HALO && p < NT) {                      // p >= 0 by construction
        out[rowbase + p] = y;
    }
}

extern "C" void kernel_launch(void* const* d_in, const int* in_sizes, int n_in,
                              void* d_out, int out_size)
{
    const float* x  = (const float*)d_in[0];   // (4, 16384) float32
    const float* mc = (const float*)d_in[1];   // (4, 16384, 25) float32
    float* out = (float*)d_out;                // (4, 16384) float32
    fir_kernel<<<NB * NTILES, THREADS>>>(x, mc, out);
}